// round 2
// baseline (speedup 1.0000x reference)
#include <cuda_runtime.h>
#include <cstddef>

#define BATCH  2
#define SEQ    2048
#define DMODEL 1024
#define NHEADS 16
#define HD     64
#define QKVDIM (3*DMODEL)

// Scratch (allocation-free rule: __device__ globals)
__device__ float g_qkv[(size_t)BATCH*SEQ*QKVDIM];   // [4096, 3072]
__device__ float g_attn[(size_t)BATCH*SEQ*DMODEL];  // [4096, 1024]

// ---------------------------------------------------------------------------
// C[M,N] = A[M,K] @ B[N,K]^T + bias[N]      (both operands K-major, "NT")
// BM=BN=128, BK=16, 256 threads, 8x8 micro-tile.
// ---------------------------------------------------------------------------
__global__ __launch_bounds__(256)
void gemm_nt_bias(const float* __restrict__ A,
                  const float* __restrict__ B,
                  const float* __restrict__ bias,
                  float* __restrict__ C,
                  int M, int N, int K)
{
    __shared__ float As[16][132];   // +4 pad keeps float4 alignment, breaks conflicts
    __shared__ float Bs[16][132];

    const int tid = threadIdx.x;
    const int tx  = tid & 15;        // 0..15  -> N direction
    const int ty  = tid >> 4;        // 0..15  -> M direction
    const int row0 = blockIdx.y * 128;
    const int col0 = blockIdx.x * 128;

    const int lr  = tid >> 2;        // 0..63 load row
    const int seg = tid & 3;         // float4 segment along K

    const float* Ag = A + (size_t)(row0 + lr) * K + (seg << 2);
    const float* Bg = B + (size_t)(col0 + lr) * K + (seg << 2);

    float acc[8][8];
    #pragma unroll
    for (int i = 0; i < 8; i++)
        #pragma unroll
        for (int j = 0; j < 8; j++) acc[i][j] = 0.f;

    for (int k0 = 0; k0 < K; k0 += 16) {
        float4 a0 = *(const float4*)(Ag + k0);
        float4 a1 = *(const float4*)(Ag + (size_t)64 * K + k0);
        float4 b0 = *(const float4*)(Bg + k0);
        float4 b1 = *(const float4*)(Bg + (size_t)64 * K + k0);

        __syncthreads();
        As[seg*4+0][lr]     = a0.x; As[seg*4+1][lr]     = a0.y;
        As[seg*4+2][lr]     = a0.z; As[seg*4+3][lr]     = a0.w;
        As[seg*4+0][lr+64]  = a1.x; As[seg*4+1][lr+64]  = a1.y;
        As[seg*4+2][lr+64]  = a1.z; As[seg*4+3][lr+64]  = a1.w;
        Bs[seg*4+0][lr]     = b0.x; Bs[seg*4+1][lr]     = b0.y;
        Bs[seg*4+2][lr]     = b0.z; Bs[seg*4+3][lr]     = b0.w;
        Bs[seg*4+0][lr+64]  = b1.x; Bs[seg*4+1][lr+64]  = b1.y;
        Bs[seg*4+2][lr+64]  = b1.z; Bs[seg*4+3][lr+64]  = b1.w;
        __syncthreads();

        #pragma unroll
        for (int k = 0; k < 16; k++) {
            float4 av0 = *(const float4*)&As[k][ty*8];
            float4 av1 = *(const float4*)&As[k][ty*8 + 4];
            float4 bv0 = *(const float4*)&Bs[k][tx*8];
            float4 bv1 = *(const float4*)&Bs[k][tx*8 + 4];
            float a[8] = {av0.x, av0.y, av0.z, av0.w, av1.x, av1.y, av1.z, av1.w};
            float bb[8] = {bv0.x, bv0.y, bv0.z, bv0.w, bv1.x, bv1.y, bv1.z, bv1.w};
            #pragma unroll
            for (int i = 0; i < 8; i++)
                #pragma unroll
                for (int j = 0; j < 8; j++)
                    acc[i][j] = fmaf(a[i], bb[j], acc[i][j]);
        }
    }

    const int crow = row0 + ty * 8;
    const int ccol = col0 + tx * 8;
    float4 bi0 = *(const float4*)(bias + ccol);
    float4 bi1 = *(const float4*)(bias + ccol + 4);
    #pragma unroll
    for (int i = 0; i < 8; i++) {
        float4 o0 = make_float4(acc[i][0] + bi0.x, acc[i][1] + bi0.y,
                                acc[i][2] + bi0.z, acc[i][3] + bi0.w);
        float4 o1 = make_float4(acc[i][4] + bi1.x, acc[i][5] + bi1.y,
                                acc[i][6] + bi1.z, acc[i][7] + bi1.w);
        *(float4*)(C + (size_t)(crow + i) * N + ccol)     = o0;
        *(float4*)(C + (size_t)(crow + i) * N + ccol + 4) = o1;
    }
}

// ---------------------------------------------------------------------------
// Causal flash attention, fp32, 1 thread per query row, 16-key KV tiles.
// qkv layout: [b*SEQ + s, 3072], q at col h*64, k at 1024+h*64, v at 2048+h*64
// out layout: [b*SEQ + s, 1024] (head-interleaved -> feeds proj GEMM directly)
// ---------------------------------------------------------------------------
__global__ __launch_bounds__(128)
void attn_kernel(const float* __restrict__ qkv, float* __restrict__ outp)
{
    const int tid = threadIdx.x;                 // 0..127
    const int qb  = blockIdx.x & 15;             // 16 q-blocks of 128
    const int h   = (blockIdx.x >> 4) & 15;
    const int b   = blockIdx.x >> 8;
    const int qi  = qb * 128 + tid;              // this thread's query index

    const float* qptr = qkv + ((size_t)(b * SEQ + qi)) * QKVDIM + h * HD;
    float q[HD], O[HD];
    #pragma unroll
    for (int d = 0; d < HD; d++) { q[d] = qptr[d] * 0.125f; O[d] = 0.f; }

    float m = -1e30f, l = 0.f;

    __shared__ float Ks[16][HD];
    __shared__ float Vs[16][HD];

    const int kend = qb * 128 + 127;             // causal limit for this block

    for (int kv0 = 0; kv0 <= kend; kv0 += 16) {
        const float* kbase = qkv + ((size_t)(b * SEQ + kv0)) * QKVDIM + DMODEL  + h * HD;
        const float* vbase = kbase + DMODEL;

        __syncthreads();
        #pragma unroll
        for (int t = 0; t < 2; t++) {
            int idx = tid + t * 128;             // 0..255 = 16 rows * 16 float4
            int r = idx >> 4, c = idx & 15;
            ((float4*)Ks)[idx] = *(const float4*)(kbase + (size_t)r * QKVDIM + c * 4);
            ((float4*)Vs)[idx] = *(const float4*)(vbase + (size_t)r * QKVDIM + c * 4);
        }
        __syncthreads();

        float s[16];
        float mnew = m;
        #pragma unroll
        for (int j = 0; j < 16; j++) {
            const float4* kr = (const float4*)Ks[j];
            float acc = 0.f;
            #pragma unroll
            for (int dd = 0; dd < 16; dd++) {
                float4 kk = kr[dd];
                acc = fmaf(q[dd*4+0], kk.x, acc);
                acc = fmaf(q[dd*4+1], kk.y, acc);
                acc = fmaf(q[dd*4+2], kk.z, acc);
                acc = fmaf(q[dd*4+3], kk.w, acc);
            }
            s[j] = (kv0 + j <= qi) ? acc : -1e30f;
            mnew = fmaxf(mnew, s[j]);
        }

        float scale = __expf(m - mnew);
        l *= scale;
        #pragma unroll
        for (int d = 0; d < HD; d++) O[d] *= scale;

        #pragma unroll
        for (int j = 0; j < 16; j++) {
            float p = __expf(s[j] - mnew);
            l += p;
            const float4* vr = (const float4*)Vs[j];
            #pragma unroll
            for (int dd = 0; dd < 16; dd++) {
                float4 vv = vr[dd];
                O[dd*4+0] = fmaf(p, vv.x, O[dd*4+0]);
                O[dd*4+1] = fmaf(p, vv.y, O[dd*4+1]);
                O[dd*4+2] = fmaf(p, vv.z, O[dd*4+2]);
                O[dd*4+3] = fmaf(p, vv.w, O[dd*4+3]);
            }
        }
        m = mnew;
    }

    const float inv = 1.f / l;
    float* op = outp + ((size_t)(b * SEQ + qi)) * DMODEL + h * HD;
    #pragma unroll
    for (int dd = 0; dd < 16; dd++) {
        float4 o = make_float4(O[dd*4+0] * inv, O[dd*4+1] * inv,
                               O[dd*4+2] * inv, O[dd*4+3] * inv);
        *(float4*)(op + dd * 4) = o;
    }
}

// ---------------------------------------------------------------------------
extern "C" void kernel_launch(void* const* d_in, const int* in_sizes, int n_in,
                              void* d_out, int out_size)
{
    const float* x    = (const float*)d_in[0];   // [2,2048,1024]
    const float* Wqkv = (const float*)d_in[1];   // [3072,1024]
    const float* bqkv = (const float*)d_in[2];   // [3072]
    const float* Wd   = (const float*)d_in[3];   // [1024,1024]
    const float* bd   = (const float*)d_in[4];   // [1024]
    // d_in[5] = mask (always 1; causal applied unconditionally)
    float* out = (float*)d_out;

    float* qkv_buf = nullptr;
    float* attn_buf = nullptr;
    cudaGetSymbolAddress((void**)&qkv_buf,  g_qkv);
    cudaGetSymbolAddress((void**)&attn_buf, g_attn);

    const int M = BATCH * SEQ;   // 4096

    // 1) QKV projection: [4096,3072] = x @ Wqkv^T + bqkv
    gemm_nt_bias<<<dim3(QKVDIM / 128, M / 128), 256>>>(
        x, Wqkv, bqkv, qkv_buf, M, QKVDIM, DMODEL);

    // 2) Causal attention -> [4096,1024]
    attn_kernel<<<BATCH * NHEADS * (SEQ / 128), 128>>>(qkv_buf, attn_buf);

    // 3) Output projection: out = attn @ Wd^T + bd
    gemm_nt_bias<<<dim3(DMODEL / 128, M / 128), 256>>>(
        attn_buf, Wd, bd, out, M, DMODEL, DMODEL);
}

// round 8
// speedup vs baseline: 3.6872x; 3.6872x over previous
#include <cuda_runtime.h>
#include <cstdint>
#include <cstddef>

#define BATCH  2
#define SEQ    2048
#define DMODEL 1024
#define NHEADS 16
#define HD     64
#define QKVDIM 3072

// Scratch (allocation-free rule: __device__ globals)
__device__ float g_qkv[(size_t)BATCH*SEQ*QKVDIM];   // [4096, 3072]
__device__ float g_attn[(size_t)BATCH*SEQ*DMODEL];  // [4096, 1024]

// ===========================================================================
// helpers
// ===========================================================================
__device__ __forceinline__ uint32_t f2tf(float f) {
    uint32_t r;
    asm("cvt.rna.tf32.f32 %0, %1;" : "=r"(r) : "f"(f));
    return r;
}
__device__ __forceinline__ float ex2(float x) {
    float y;
    asm("ex2.approx.f32 %0, %1;" : "=f"(y) : "f"(x));
    return y;
}
// D += A*B  (m16n8k8 tf32, row.col)
__device__ __forceinline__ void mma_tf32(float c[4],
                                         uint32_t a0, uint32_t a1,
                                         uint32_t a2, uint32_t a3,
                                         uint32_t b0, uint32_t b1)
{
    asm volatile(
        "mma.sync.aligned.m16n8k8.row.col.f32.tf32.tf32.f32 "
        "{%0,%1,%2,%3},{%4,%5,%6,%7},{%8,%9},{%0,%1,%2,%3};"
        : "+f"(c[0]), "+f"(c[1]), "+f"(c[2]), "+f"(c[3])
        : "r"(a0), "r"(a1), "r"(a2), "r"(a3), "r"(b0), "r"(b1));
}

// ===========================================================================
// tf32 mma GEMM: C[M,N] = A[M,K] @ B[N,K]^T + bias[N]
// BM=BN=128, BK=16, 256 threads (8 warps), warp tile 32m x 64n.
// SMEM tiles [128 rows][16 k] with row stride 20 words (conflict-free frags).
// ===========================================================================
#define GSTRIDE 20

__global__ __launch_bounds__(256)
void gemm_mma(const float* __restrict__ A,
              const float* __restrict__ B,
              const float* __restrict__ bias,
              float* __restrict__ C,
              int M, int N, int K)
{
    __shared__ uint32_t As[128 * GSTRIDE];
    __shared__ uint32_t Bs[128 * GSTRIDE];

    const int tid  = threadIdx.x;
    const int lane = tid & 31;
    const int wid  = tid >> 5;
    const int g    = lane >> 2;      // groupID
    const int t    = lane & 3;       // thread-in-group
    const int wm   = wid >> 1;       // 0..3
    const int wn   = wid & 1;        // 0..1

    const int row0 = blockIdx.y * 128;
    const int col0 = blockIdx.x * 128;
    const int NT   = K / 16;

    // Global load geometry: 2 float4 per tile per thread for A and B.
    // f = i*256 + tid : row = f>>2 (0..127), c4 = f&3
    const int lr0 = tid >> 2, lc = (tid & 3) * 4;
    const float* Ag0 = A + (size_t)(row0 + lr0) * K + lc;
    const float* Ag1 = A + (size_t)(row0 + lr0 + 64) * K + lc;
    const float* Bg0 = B + (size_t)(col0 + lr0) * K + lc;
    const float* Bg1 = B + (size_t)(col0 + lr0 + 64) * K + lc;
    const int sidx0 = lr0 * GSTRIDE + lc;
    const int sidx1 = (lr0 + 64) * GSTRIDE + lc;

    float acc[2][8][4];
    #pragma unroll
    for (int i = 0; i < 2; i++)
        #pragma unroll
        for (int j = 0; j < 8; j++)
            #pragma unroll
            for (int c = 0; c < 4; c++) acc[i][j][c] = 0.f;

    // prologue prefetch
    float4 ar0 = *(const float4*)(Ag0);
    float4 ar1 = *(const float4*)(Ag1);
    float4 br0 = *(const float4*)(Bg0);
    float4 br1 = *(const float4*)(Bg1);

    for (int kt = 0; kt < NT; kt++) {
        if (kt > 0) __syncthreads();
        // store current tile (converted to tf32)
        {
            uint4 u;
            u.x = f2tf(ar0.x); u.y = f2tf(ar0.y); u.z = f2tf(ar0.z); u.w = f2tf(ar0.w);
            *(uint4*)&As[sidx0] = u;
            u.x = f2tf(ar1.x); u.y = f2tf(ar1.y); u.z = f2tf(ar1.z); u.w = f2tf(ar1.w);
            *(uint4*)&As[sidx1] = u;
            u.x = f2tf(br0.x); u.y = f2tf(br0.y); u.z = f2tf(br0.z); u.w = f2tf(br0.w);
            *(uint4*)&Bs[sidx0] = u;
            u.x = f2tf(br1.x); u.y = f2tf(br1.y); u.z = f2tf(br1.z); u.w = f2tf(br1.w);
            *(uint4*)&Bs[sidx1] = u;
        }
        __syncthreads();

        if (kt + 1 < NT) {
            const int ko = (kt + 1) * 16;
            ar0 = *(const float4*)(Ag0 + ko);
            ar1 = *(const float4*)(Ag1 + ko);
            br0 = *(const float4*)(Bg0 + ko);
            br1 = *(const float4*)(Bg1 + ko);
        }

        #pragma unroll
        for (int kk = 0; kk < 16; kk += 8) {
            uint32_t a[2][4];
            #pragma unroll
            for (int mf = 0; mf < 2; mf++) {
                const int rb = wm * 32 + mf * 16;
                a[mf][0] = As[(rb + g)     * GSTRIDE + kk + t];
                a[mf][1] = As[(rb + g + 8) * GSTRIDE + kk + t];
                a[mf][2] = As[(rb + g)     * GSTRIDE + kk + t + 4];
                a[mf][3] = As[(rb + g + 8) * GSTRIDE + kk + t + 4];
            }
            #pragma unroll
            for (int nf = 0; nf < 8; nf++) {
                const int nb = wn * 64 + nf * 8 + g;
                uint32_t b0 = Bs[nb * GSTRIDE + kk + t];
                uint32_t b1 = Bs[nb * GSTRIDE + kk + t + 4];
                mma_tf32(acc[0][nf], a[0][0], a[0][1], a[0][2], a[0][3], b0, b1);
                mma_tf32(acc[1][nf], a[1][0], a[1][1], a[1][2], a[1][3], b0, b1);
            }
        }
    }

    // epilogue: add bias, write
    #pragma unroll
    for (int mf = 0; mf < 2; mf++) {
        const int r0 = row0 + wm * 32 + mf * 16 + g;
        #pragma unroll
        for (int nf = 0; nf < 8; nf++) {
            const int col = col0 + wn * 64 + nf * 8 + 2 * t;
            const float b0 = bias[col], b1 = bias[col + 1];
            float2 v0 = make_float2(acc[mf][nf][0] + b0, acc[mf][nf][1] + b1);
            float2 v1 = make_float2(acc[mf][nf][2] + b0, acc[mf][nf][3] + b1);
            *(float2*)(C + (size_t)r0 * N + col)       = v0;
            *(float2*)(C + (size_t)(r0 + 8) * N + col) = v1;
        }
    }
}

// ===========================================================================
// tf32 mma causal flash attention.
// CTA = one (b, h, 64-query tile). 128 threads, 4 warps, warp = 16 q rows.
// kv blocks of 64. S = Q K^T via mma; P -> SMEM; O += P V via mma.
// Q pre-scaled by (1/8)*log2(e); softmax in exp2 domain.
// SMEM strides: Q/K/P = 68 words, V = 72 words (bank-conflict-free frags).
// ===========================================================================
#define QS_OFF 0
#define KS_OFF (64 * 68)
#define VS_OFF (KS_OFF + 64 * 68)
#define PS_OFF (VS_OFF + 64 * 72)
#define ATTN_SMEM_WORDS (PS_OFF + 64 * 68)
#define ATTN_SMEM_BYTES (ATTN_SMEM_WORDS * 4)   // 70656

__global__ __launch_bounds__(128)
void attn_mma(const float* __restrict__ qkv, float* __restrict__ outp)
{
    extern __shared__ uint32_t sm[];
    uint32_t* Qs = sm + QS_OFF;
    uint32_t* Ks = sm + KS_OFF;
    uint32_t* Vs = sm + VS_OFF;
    uint32_t* Ps = sm + PS_OFF;

    const int tid  = threadIdx.x;
    const int lane = tid & 31;
    const int w    = tid >> 5;       // 0..3
    const int g    = lane >> 2;
    const int t    = lane & 3;

    const int qt = blockIdx.x;       // 0..31
    const int h  = blockIdx.y;       // 0..15
    const int b  = blockIdx.z;       // 0..1
    const int q0 = qt * 64;

    const float SCALE = 0.125f * 1.44269504088896f;   // (1/sqrt(64)) * log2(e)

    // ---- load Q tile (scaled, tf32) ----
    {
        const float* qb = qkv + (size_t)(b * SEQ + q0) * QKVDIM + h * HD;
        #pragma unroll
        for (int i = 0; i < 8; i++) {
            int f = i * 128 + tid;
            int row = f >> 4, c4 = (f & 15) * 4;
            float4 v = *(const float4*)(qb + (size_t)row * QKVDIM + c4);
            uint4 u;
            u.x = f2tf(v.x * SCALE); u.y = f2tf(v.y * SCALE);
            u.z = f2tf(v.z * SCALE); u.w = f2tf(v.w * SCALE);
            *(uint4*)&Qs[row * 68 + c4] = u;
        }
    }

    float m0 = -1e30f, m1 = -1e30f, l0 = 0.f, l1 = 0.f;
    float O[8][4];
    #pragma unroll
    for (int nf = 0; nf < 8; nf++)
        #pragma unroll
        for (int c = 0; c < 4; c++) O[nf][c] = 0.f;

    const int arow = (w * 16 + g) * 68;       // Q/P a-frag row base
    const int arow8 = (w * 16 + g + 8) * 68;

    for (int kv0 = 0; kv0 <= q0; kv0 += 64) {
        __syncthreads();
        // ---- load K, V tiles ----
        {
            const float* kb = qkv + (size_t)(b * SEQ + kv0) * QKVDIM + DMODEL + h * HD;
            const float* vb = kb + DMODEL;
            #pragma unroll
            for (int i = 0; i < 8; i++) {
                int f = i * 128 + tid;
                int row = f >> 4, c4 = (f & 15) * 4;
                float4 kv4 = *(const float4*)(kb + (size_t)row * QKVDIM + c4);
                float4 vv4 = *(const float4*)(vb + (size_t)row * QKVDIM + c4);
                uint4 u;
                u.x = f2tf(kv4.x); u.y = f2tf(kv4.y); u.z = f2tf(kv4.z); u.w = f2tf(kv4.w);
                *(uint4*)&Ks[row * 68 + c4] = u;
                u.x = f2tf(vv4.x); u.y = f2tf(vv4.y); u.z = f2tf(vv4.z); u.w = f2tf(vv4.w);
                *(uint4*)&Vs[row * 72 + c4] = u;
            }
        }
        __syncthreads();

        // ---- S = Q K^T  (warp: m16 x n64 x k64) ----
        float s[8][4];
        #pragma unroll
        for (int nf = 0; nf < 8; nf++)
            #pragma unroll
            for (int c = 0; c < 4; c++) s[nf][c] = 0.f;

        #pragma unroll
        for (int kk = 0; kk < 64; kk += 8) {
            uint32_t a0 = Qs[arow  + kk + t];
            uint32_t a1 = Qs[arow8 + kk + t];
            uint32_t a2 = Qs[arow  + kk + t + 4];
            uint32_t a3 = Qs[arow8 + kk + t + 4];
            #pragma unroll
            for (int nf = 0; nf < 8; nf++) {
                uint32_t b0 = Ks[(nf * 8 + g) * 68 + kk + t];
                uint32_t b1 = Ks[(nf * 8 + g) * 68 + kk + t + 4];
                mma_tf32(s[nf], a0, a1, a2, a3, b0, b1);
            }
        }

        // ---- causal mask (diagonal block only) ----
        const int r0 = q0 + w * 16 + g;
        const int r1 = r0 + 8;
        if (kv0 == q0) {
            #pragma unroll
            for (int nf = 0; nf < 8; nf++) {
                int c0 = kv0 + nf * 8 + 2 * t;
                if (c0     > r0) s[nf][0] = -1e30f;
                if (c0 + 1 > r0) s[nf][1] = -1e30f;
                if (c0     > r1) s[nf][2] = -1e30f;
                if (c0 + 1 > r1) s[nf][3] = -1e30f;
            }
        }

        // ---- online softmax (exp2 domain) ----
        float rm0 = -1e30f, rm1 = -1e30f;
        #pragma unroll
        for (int nf = 0; nf < 8; nf++) {
            rm0 = fmaxf(rm0, fmaxf(s[nf][0], s[nf][1]));
            rm1 = fmaxf(rm1, fmaxf(s[nf][2], s[nf][3]));
        }
        rm0 = fmaxf(rm0, __shfl_xor_sync(0xffffffffu, rm0, 1));
        rm0 = fmaxf(rm0, __shfl_xor_sync(0xffffffffu, rm0, 2));
        rm1 = fmaxf(rm1, __shfl_xor_sync(0xffffffffu, rm1, 1));
        rm1 = fmaxf(rm1, __shfl_xor_sync(0xffffffffu, rm1, 2));

        float mn0 = fmaxf(m0, rm0), mn1 = fmaxf(m1, rm1);
        float f0 = ex2(m0 - mn0), f1 = ex2(m1 - mn1);
        l0 *= f0; l1 *= f1;
        #pragma unroll
        for (int nf = 0; nf < 8; nf++) {
            O[nf][0] *= f0; O[nf][1] *= f0;
            O[nf][2] *= f1; O[nf][3] *= f1;
        }

        float sum0 = 0.f, sum1 = 0.f;
        #pragma unroll
        for (int nf = 0; nf < 8; nf++) {
            float p0 = ex2(s[nf][0] - mn0);
            float p1 = ex2(s[nf][1] - mn0);
            float p2 = ex2(s[nf][2] - mn1);
            float p3 = ex2(s[nf][3] - mn1);
            sum0 += p0 + p1; sum1 += p2 + p3;
            int ci = nf * 8 + 2 * t;
            Ps[arow  + ci] = f2tf(p0); Ps[arow  + ci + 1] = f2tf(p1);
            Ps[arow8 + ci] = f2tf(p2); Ps[arow8 + ci + 1] = f2tf(p3);
        }
        sum0 += __shfl_xor_sync(0xffffffffu, sum0, 1);
        sum0 += __shfl_xor_sync(0xffffffffu, sum0, 2);
        sum1 += __shfl_xor_sync(0xffffffffu, sum1, 1);
        sum1 += __shfl_xor_sync(0xffffffffu, sum1, 2);
        l0 += sum0; l1 += sum1;
        m0 = mn0; m1 = mn1;

        __syncwarp();

        // ---- O += P V  (warp: m16 x n64(hd) x k64) ----
        #pragma unroll
        for (int kk = 0; kk < 64; kk += 8) {
            uint32_t a0 = Ps[arow  + kk + t];
            uint32_t a1 = Ps[arow8 + kk + t];
            uint32_t a2 = Ps[arow  + kk + t + 4];
            uint32_t a3 = Ps[arow8 + kk + t + 4];
            #pragma unroll
            for (int nf = 0; nf < 8; nf++) {
                uint32_t b0 = Vs[(kk + t) * 72 + nf * 8 + g];
                uint32_t b1 = Vs[(kk + t + 4) * 72 + nf * 8 + g];
                mma_tf32(O[nf], a0, a1, a2, a3, b0, b1);
            }
        }
    }

    // ---- epilogue ----
    const float inv0 = 1.f / l0, inv1 = 1.f / l1;
    const size_t orow0 = (size_t)(b * SEQ + q0 + w * 16 + g);
    const size_t orow1 = orow0 + 8;
    #pragma unroll
    for (int nf = 0; nf < 8; nf++) {
        const int col = h * HD + nf * 8 + 2 * t;
        *(float2*)(outp + orow0 * DMODEL + col) =
            make_float2(O[nf][0] * inv0, O[nf][1] * inv0);
        *(float2*)(outp + orow1 * DMODEL + col) =
            make_float2(O[nf][2] * inv1, O[nf][3] * inv1);
    }
}

// ---------------------------------------------------------------------------
extern "C" void kernel_launch(void* const* d_in, const int* in_sizes, int n_in,
                              void* d_out, int out_size)
{
    const float* x    = (const float*)d_in[0];   // [2,2048,1024]
    const float* Wqkv = (const float*)d_in[1];   // [3072,1024]
    const float* bqkv = (const float*)d_in[2];   // [3072]
    const float* Wd   = (const float*)d_in[3];   // [1024,1024]
    const float* bd   = (const float*)d_in[4];   // [1024]
    float* out = (float*)d_out;

    float* qkv_buf = nullptr;
    float* attn_buf = nullptr;
    cudaGetSymbolAddress((void**)&qkv_buf,  g_qkv);
    cudaGetSymbolAddress((void**)&attn_buf, g_attn);

    const int M = BATCH * SEQ;   // 4096

    cudaFuncSetAttribute(attn_mma,
                         cudaFuncAttributeMaxDynamicSharedMemorySize,
                         ATTN_SMEM_BYTES);

    // 1) QKV projection: [4096,3072] = x @ Wqkv^T + bqkv
    gemm_mma<<<dim3(QKVDIM / 128, M / 128), 256>>>(
        x, Wqkv, bqkv, qkv_buf, M, QKVDIM, DMODEL);

    // 2) Causal attention -> [4096,1024]
    attn_mma<<<dim3(SEQ / 64, NHEADS, BATCH), 128, ATTN_SMEM_BYTES>>>(
        qkv_buf, attn_buf);

    // 3) Output projection: out = attn @ Wd^T + bd
    gemm_mma<<<dim3(DMODEL / 128, M / 128), 256>>>(
        attn_buf, Wd, bd, out, M, DMODEL, DMODEL);
}

// round 9
// speedup vs baseline: 4.2749x; 1.1594x over previous
#include <cuda_runtime.h>
#include <cstdint>
#include <cstddef>

#define BATCH  2
#define SEQ    2048
#define DMODEL 1024
#define NHEADS 16
#define HD     64
#define QKVDIM 3072

// Scratch (allocation-free rule: __device__ globals)
__device__ float g_qkv[(size_t)BATCH*SEQ*QKVDIM];    // [4096, 3072]
__device__ float g_attn[(size_t)BATCH*SEQ*DMODEL];   // [4096, 1024] (tf32-rounded)
__device__ float g_xr[(size_t)BATCH*SEQ*DMODEL];     // tf32-rounded x
__device__ float g_wqkvr[(size_t)QKVDIM*DMODEL];     // tf32-rounded Wqkv
__device__ float g_wdr[(size_t)DMODEL*DMODEL];       // tf32-rounded Wd

// ===========================================================================
// helpers
// ===========================================================================
__device__ __forceinline__ uint32_t smem_u32(const void* p) {
    uint32_t a;
    asm("{ .reg .u64 t; cvta.to.shared.u64 t, %1; cvt.u32.u64 %0, t; }"
        : "=r"(a) : "l"(p));
    return a;
}
__device__ __forceinline__ uint32_t f2tf(float f) {
    uint32_t r;
    asm("cvt.rna.tf32.f32 %0, %1;" : "=r"(r) : "f"(f));
    return r;
}
__device__ __forceinline__ float ex2(float x) {
    float y;
    asm("ex2.approx.f32 %0, %1;" : "=f"(y) : "f"(x));
    return y;
}
// D += A*B  (m16n8k8 tf32, row.col)
__device__ __forceinline__ void mma_tf32(float c[4],
                                         uint32_t a0, uint32_t a1,
                                         uint32_t a2, uint32_t a3,
                                         uint32_t b0, uint32_t b1)
{
    asm volatile(
        "mma.sync.aligned.m16n8k8.row.col.f32.tf32.tf32.f32 "
        "{%0,%1,%2,%3},{%4,%5,%6,%7},{%8,%9},{%0,%1,%2,%3};"
        : "+f"(c[0]), "+f"(c[1]), "+f"(c[2]), "+f"(c[3])
        : "r"(a0), "r"(a1), "r"(a2), "r"(a3), "r"(b0), "r"(b1));
}
#define CP_ASYNC16(dst_u32, src_ptr) \
    asm volatile("cp.async.cg.shared.global [%0], [%1], 16;" \
                 :: "r"(dst_u32), "l"(src_ptr))
#define CP_COMMIT() asm volatile("cp.async.commit_group;" ::: "memory")
#define CP_WAIT2()  asm volatile("cp.async.wait_group 2;" ::: "memory")

// ===========================================================================
// elementwise tf32 pre-rounding (rna) — feeds the cp.async GEMM path
// ===========================================================================
__global__ __launch_bounds__(256)
void round_tf32_kernel(const float* __restrict__ in, float* __restrict__ out,
                       int n)
{
    int i = (blockIdx.x * 256 + threadIdx.x) * 4;
    if (i < n) {
        float4 v = *(const float4*)(in + i);
        float4 o;
        o.x = __uint_as_float(f2tf(v.x));
        o.y = __uint_as_float(f2tf(v.y));
        o.z = __uint_as_float(f2tf(v.z));
        o.w = __uint_as_float(f2tf(v.w));
        *(float4*)(out + i) = o;
    }
}

// ===========================================================================
// tf32 mma GEMM, 4-stage cp.async pipeline.
// C[M,N] = A[M,K] @ B[N,K]^T + bias[N]; A,B pre-rounded to tf32.
// BM=BN=128, BK=16, 128 threads (4 warps), warp tile 64x64.
// SMEM row stride 20 words (conflict-free fragment loads).
// ===========================================================================
#define GSTRIDE 20
#define STAGES 4
#define STAGE_WORDS (128 * GSTRIDE)         // 2560 words per matrix per stage
#define STAGE_PAIR  (2 * STAGE_WORDS)       // 5120
#define GEMM_SMEM_BYTES (STAGES * STAGE_PAIR * 4)   // 81920

__global__ __launch_bounds__(128, 2)
void gemm_mma(const float* __restrict__ A,
              const float* __restrict__ B,
              const float* __restrict__ bias,
              float* __restrict__ C,
              int M, int N, int K)
{
    extern __shared__ uint32_t sm[];
    const uint32_t smem_base = smem_u32(sm);

    const int tid  = threadIdx.x;
    const int lane = tid & 31;
    const int wid  = tid >> 5;
    const int g    = lane >> 2;
    const int t    = lane & 3;
    const int wm   = wid >> 1;      // 0..1
    const int wn   = wid & 1;       // 0..1

    const int row0 = blockIdx.y * 128;
    const int col0 = blockIdx.x * 128;
    const int NT   = K / 16;

    // cp.async geometry: 4 x 16B per matrix per thread per stage.
    // chunk i: row = i*32 + (tid>>2), float4-col = tid&3
    const int lr = tid >> 2;        // 0..31
    const int lc = tid & 3;         // 0..3
    const float* Ab = A + (size_t)row0 * K;
    const float* Bb = B + (size_t)col0 * K;
    uint32_t so[4];
    #pragma unroll
    for (int i = 0; i < 4; i++)
        so[i] = ((i * 32 + lr) * GSTRIDE + lc * 4) * 4;   // byte offset

    #define ISSUE_STAGE(kt, s) do { \
        const uint32_t sa = smem_base + (uint32_t)(s) * (STAGE_PAIR * 4); \
        const uint32_t sb = sa + STAGE_WORDS * 4; \
        const int ko = (kt) * 16 + lc * 4; \
        _Pragma("unroll") \
        for (int i = 0; i < 4; i++) { \
            CP_ASYNC16(sa + so[i], Ab + (size_t)(i * 32 + lr) * K + ko); \
            CP_ASYNC16(sb + so[i], Bb + (size_t)(i * 32 + lr) * K + ko); \
        } \
    } while (0)

    float acc[4][8][4];
    #pragma unroll
    for (int mf = 0; mf < 4; mf++)
        #pragma unroll
        for (int nf = 0; nf < 8; nf++)
            #pragma unroll
            for (int c = 0; c < 4; c++) acc[mf][nf][c] = 0.f;

    // prologue: stages 0..2 in flight
    ISSUE_STAGE(0, 0); CP_COMMIT();
    ISSUE_STAGE(1, 1); CP_COMMIT();
    ISSUE_STAGE(2, 2); CP_COMMIT();

    for (int kt = 0; kt < NT; kt++) {
        if (kt + 3 < NT) ISSUE_STAGE(kt + 3, (kt + 3) & 3);
        CP_COMMIT();
        CP_WAIT2();            // stages <= kt complete, 2 in flight
        __syncthreads();

        const uint32_t* sA = sm + (kt & 3) * STAGE_PAIR;
        const uint32_t* sB = sA + STAGE_WORDS;

        #pragma unroll
        for (int kk = 0; kk < 16; kk += 8) {
            uint32_t a[4][4], bf[8][2];
            #pragma unroll
            for (int mf = 0; mf < 4; mf++) {
                const int rb = wm * 64 + mf * 16;
                a[mf][0] = sA[(rb + g)     * GSTRIDE + kk + t];
                a[mf][1] = sA[(rb + g + 8) * GSTRIDE + kk + t];
                a[mf][2] = sA[(rb + g)     * GSTRIDE + kk + t + 4];
                a[mf][3] = sA[(rb + g + 8) * GSTRIDE + kk + t + 4];
            }
            #pragma unroll
            for (int nf = 0; nf < 8; nf++) {
                const int nb = wn * 64 + nf * 8 + g;
                bf[nf][0] = sB[nb * GSTRIDE + kk + t];
                bf[nf][1] = sB[nb * GSTRIDE + kk + t + 4];
            }
            #pragma unroll
            for (int mf = 0; mf < 4; mf++)
                #pragma unroll
                for (int nf = 0; nf < 8; nf++)
                    mma_tf32(acc[mf][nf], a[mf][0], a[mf][1], a[mf][2], a[mf][3],
                             bf[nf][0], bf[nf][1]);
        }
        __syncthreads();
    }

    // epilogue: add bias, write
    #pragma unroll
    for (int mf = 0; mf < 4; mf++) {
        const int r0 = row0 + wm * 64 + mf * 16 + g;
        #pragma unroll
        for (int nf = 0; nf < 8; nf++) {
            const int col = col0 + wn * 64 + nf * 8 + 2 * t;
            const float b0 = bias[col], b1 = bias[col + 1];
            *(float2*)(C + (size_t)r0 * N + col) =
                make_float2(acc[mf][nf][0] + b0, acc[mf][nf][1] + b1);
            *(float2*)(C + (size_t)(r0 + 8) * N + col) =
                make_float2(acc[mf][nf][2] + b0, acc[mf][nf][3] + b1);
        }
    }
}

// ===========================================================================
// tf32 mma causal flash attention (as R8; epilogue now writes tf32-rounded
// values so the cp.async proj GEMM sees pre-rounded input).
// ===========================================================================
#define QS_OFF 0
#define KS_OFF (64 * 68)
#define VS_OFF (KS_OFF + 64 * 68)
#define PS_OFF (VS_OFF + 64 * 72)
#define ATTN_SMEM_WORDS (PS_OFF + 64 * 68)
#define ATTN_SMEM_BYTES (ATTN_SMEM_WORDS * 4)   // 70656

__global__ __launch_bounds__(128)
void attn_mma(const float* __restrict__ qkv, float* __restrict__ outp)
{
    extern __shared__ uint32_t smab[];
    uint32_t* Qs = smab + QS_OFF;
    uint32_t* Ks = smab + KS_OFF;
    uint32_t* Vs = smab + VS_OFF;
    uint32_t* Ps = smab + PS_OFF;

    const int tid  = threadIdx.x;
    const int lane = tid & 31;
    const int w    = tid >> 5;
    const int g    = lane >> 2;
    const int t    = lane & 3;

    const int qt = blockIdx.x;
    const int h  = blockIdx.y;
    const int b  = blockIdx.z;
    const int q0 = qt * 64;

    const float SCALE = 0.125f * 1.44269504088896f;

    {
        const float* qb = qkv + (size_t)(b * SEQ + q0) * QKVDIM + h * HD;
        #pragma unroll
        for (int i = 0; i < 8; i++) {
            int f = i * 128 + tid;
            int row = f >> 4, c4 = (f & 15) * 4;
            float4 v = *(const float4*)(qb + (size_t)row * QKVDIM + c4);
            uint4 u;
            u.x = f2tf(v.x * SCALE); u.y = f2tf(v.y * SCALE);
            u.z = f2tf(v.z * SCALE); u.w = f2tf(v.w * SCALE);
            *(uint4*)&Qs[row * 68 + c4] = u;
        }
    }

    float m0 = -1e30f, m1 = -1e30f, l0 = 0.f, l1 = 0.f;
    float O[8][4];
    #pragma unroll
    for (int nf = 0; nf < 8; nf++)
        #pragma unroll
        for (int c = 0; c < 4; c++) O[nf][c] = 0.f;

    const int arow  = (w * 16 + g) * 68;
    const int arow8 = (w * 16 + g + 8) * 68;

    for (int kv0 = 0; kv0 <= q0; kv0 += 64) {
        __syncthreads();
        {
            const float* kb = qkv + (size_t)(b * SEQ + kv0) * QKVDIM + DMODEL + h * HD;
            const float* vb = kb + DMODEL;
            #pragma unroll
            for (int i = 0; i < 8; i++) {
                int f = i * 128 + tid;
                int row = f >> 4, c4 = (f & 15) * 4;
                float4 kv4 = *(const float4*)(kb + (size_t)row * QKVDIM + c4);
                float4 vv4 = *(const float4*)(vb + (size_t)row * QKVDIM + c4);
                uint4 u;
                u.x = f2tf(kv4.x); u.y = f2tf(kv4.y); u.z = f2tf(kv4.z); u.w = f2tf(kv4.w);
                *(uint4*)&Ks[row * 68 + c4] = u;
                u.x = f2tf(vv4.x); u.y = f2tf(vv4.y); u.z = f2tf(vv4.z); u.w = f2tf(vv4.w);
                *(uint4*)&Vs[row * 72 + c4] = u;
            }
        }
        __syncthreads();

        float s[8][4];
        #pragma unroll
        for (int nf = 0; nf < 8; nf++)
            #pragma unroll
            for (int c = 0; c < 4; c++) s[nf][c] = 0.f;

        #pragma unroll
        for (int kk = 0; kk < 64; kk += 8) {
            uint32_t a0 = Qs[arow  + kk + t];
            uint32_t a1 = Qs[arow8 + kk + t];
            uint32_t a2 = Qs[arow  + kk + t + 4];
            uint32_t a3 = Qs[arow8 + kk + t + 4];
            #pragma unroll
            for (int nf = 0; nf < 8; nf++) {
                uint32_t b0 = Ks[(nf * 8 + g) * 68 + kk + t];
                uint32_t b1 = Ks[(nf * 8 + g) * 68 + kk + t + 4];
                mma_tf32(s[nf], a0, a1, a2, a3, b0, b1);
            }
        }

        const int r0 = q0 + w * 16 + g;
        const int r1 = r0 + 8;
        if (kv0 == q0) {
            #pragma unroll
            for (int nf = 0; nf < 8; nf++) {
                int c0 = kv0 + nf * 8 + 2 * t;
                if (c0     > r0) s[nf][0] = -1e30f;
                if (c0 + 1 > r0) s[nf][1] = -1e30f;
                if (c0     > r1) s[nf][2] = -1e30f;
                if (c0 + 1 > r1) s[nf][3] = -1e30f;
            }
        }

        float rm0 = -1e30f, rm1 = -1e30f;
        #pragma unroll
        for (int nf = 0; nf < 8; nf++) {
            rm0 = fmaxf(rm0, fmaxf(s[nf][0], s[nf][1]));
            rm1 = fmaxf(rm1, fmaxf(s[nf][2], s[nf][3]));
        }
        rm0 = fmaxf(rm0, __shfl_xor_sync(0xffffffffu, rm0, 1));
        rm0 = fmaxf(rm0, __shfl_xor_sync(0xffffffffu, rm0, 2));
        rm1 = fmaxf(rm1, __shfl_xor_sync(0xffffffffu, rm1, 1));
        rm1 = fmaxf(rm1, __shfl_xor_sync(0xffffffffu, rm1, 2));

        float mn0 = fmaxf(m0, rm0), mn1 = fmaxf(m1, rm1);
        float f0 = ex2(m0 - mn0), f1 = ex2(m1 - mn1);
        l0 *= f0; l1 *= f1;
        #pragma unroll
        for (int nf = 0; nf < 8; nf++) {
            O[nf][0] *= f0; O[nf][1] *= f0;
            O[nf][2] *= f1; O[nf][3] *= f1;
        }

        float sum0 = 0.f, sum1 = 0.f;
        #pragma unroll
        for (int nf = 0; nf < 8; nf++) {
            float p0 = ex2(s[nf][0] - mn0);
            float p1 = ex2(s[nf][1] - mn0);
            float p2 = ex2(s[nf][2] - mn1);
            float p3 = ex2(s[nf][3] - mn1);
            sum0 += p0 + p1; sum1 += p2 + p3;
            int ci = nf * 8 + 2 * t;
            Ps[arow  + ci] = f2tf(p0); Ps[arow  + ci + 1] = f2tf(p1);
            Ps[arow8 + ci] = f2tf(p2); Ps[arow8 + ci + 1] = f2tf(p3);
        }
        sum0 += __shfl_xor_sync(0xffffffffu, sum0, 1);
        sum0 += __shfl_xor_sync(0xffffffffu, sum0, 2);
        sum1 += __shfl_xor_sync(0xffffffffu, sum1, 1);
        sum1 += __shfl_xor_sync(0xffffffffu, sum1, 2);
        l0 += sum0; l1 += sum1;
        m0 = mn0; m1 = mn1;

        __syncwarp();

        #pragma unroll
        for (int kk = 0; kk < 64; kk += 8) {
            uint32_t a0 = Ps[arow  + kk + t];
            uint32_t a1 = Ps[arow8 + kk + t];
            uint32_t a2 = Ps[arow  + kk + t + 4];
            uint32_t a3 = Ps[arow8 + kk + t + 4];
            #pragma unroll
            for (int nf = 0; nf < 8; nf++) {
                uint32_t b0 = Vs[(kk + t) * 72 + nf * 8 + g];
                uint32_t b1 = Vs[(kk + t + 4) * 72 + nf * 8 + g];
                mma_tf32(O[nf], a0, a1, a2, a3, b0, b1);
            }
        }
    }

    // epilogue: write tf32-rounded (feeds cp.async proj GEMM)
    const float inv0 = 1.f / l0, inv1 = 1.f / l1;
    const size_t orow0 = (size_t)(b * SEQ + q0 + w * 16 + g);
    const size_t orow1 = orow0 + 8;
    #pragma unroll
    for (int nf = 0; nf < 8; nf++) {
        const int col = h * HD + nf * 8 + 2 * t;
        *(float2*)(outp + orow0 * DMODEL + col) =
            make_float2(__uint_as_float(f2tf(O[nf][0] * inv0)),
                        __uint_as_float(f2tf(O[nf][1] * inv0)));
        *(float2*)(outp + orow1 * DMODEL + col) =
            make_float2(__uint_as_float(f2tf(O[nf][2] * inv1)),
                        __uint_as_float(f2tf(O[nf][3] * inv1)));
    }
}

// ---------------------------------------------------------------------------
extern "C" void kernel_launch(void* const* d_in, const int* in_sizes, int n_in,
                              void* d_out, int out_size)
{
    const float* x    = (const float*)d_in[0];
    const float* Wqkv = (const float*)d_in[1];
    const float* bqkv = (const float*)d_in[2];
    const float* Wd   = (const float*)d_in[3];
    const float* bd   = (const float*)d_in[4];
    float* out = (float*)d_out;

    float *qkv_buf, *attn_buf, *xr, *wqkvr, *wdr;
    cudaGetSymbolAddress((void**)&qkv_buf,  g_qkv);
    cudaGetSymbolAddress((void**)&attn_buf, g_attn);
    cudaGetSymbolAddress((void**)&xr,       g_xr);
    cudaGetSymbolAddress((void**)&wqkvr,    g_wqkvr);
    cudaGetSymbolAddress((void**)&wdr,      g_wdr);

    const int M = BATCH * SEQ;   // 4096

    cudaFuncSetAttribute(gemm_mma,
                         cudaFuncAttributeMaxDynamicSharedMemorySize,
                         GEMM_SMEM_BYTES);
    cudaFuncSetAttribute(attn_mma,
                         cudaFuncAttributeMaxDynamicSharedMemorySize,
                         ATTN_SMEM_BYTES);

    // 0) pre-round GEMM inputs to tf32 (rna)
    const int nx = M * DMODEL, nwq = QKVDIM * DMODEL, nwd = DMODEL * DMODEL;
    round_tf32_kernel<<<(nx / 4 + 255) / 256, 256>>>(x, xr, nx);
    round_tf32_kernel<<<(nwq / 4 + 255) / 256, 256>>>(Wqkv, wqkvr, nwq);
    round_tf32_kernel<<<(nwd / 4 + 255) / 256, 256>>>(Wd, wdr, nwd);

    // 1) QKV projection
    gemm_mma<<<dim3(QKVDIM / 128, M / 128), 128, GEMM_SMEM_BYTES>>>(
        xr, wqkvr, bqkv, qkv_buf, M, QKVDIM, DMODEL);

    // 2) Causal attention
    attn_mma<<<dim3(SEQ / 64, NHEADS, BATCH), 128, ATTN_SMEM_BYTES>>>(
        qkv_buf, attn_buf);

    // 3) Output projection
    gemm_mma<<<dim3(DMODEL / 128, M / 128), 128, GEMM_SMEM_BYTES>>>(
        attn_buf, wdr, bd, out, M, DMODEL, DMODEL);
}

// round 10
// speedup vs baseline: 5.1282x; 1.1996x over previous
#include <cuda_runtime.h>
#include <cstdint>
#include <cstddef>

#define BATCH  2
#define SEQ    2048
#define DMODEL 1024
#define NHEADS 16
#define HD     64
#define QKVDIM 3072

// Scratch (allocation-free rule: __device__ globals)
__device__ float g_qkv[(size_t)BATCH*SEQ*QKVDIM];    // [4096, 3072] tf32-rounded
__device__ float g_attn[(size_t)BATCH*SEQ*DMODEL];   // [4096, 1024] tf32-rounded
__device__ float g_xr[(size_t)BATCH*SEQ*DMODEL];     // tf32-rounded x
__device__ float g_wqkvr[(size_t)QKVDIM*DMODEL];     // tf32-rounded Wqkv
__device__ float g_wdr[(size_t)DMODEL*DMODEL];       // tf32-rounded Wd

// ===========================================================================
// helpers
// ===========================================================================
__device__ __forceinline__ uint32_t smem_u32(const void* p) {
    uint32_t a;
    asm("{ .reg .u64 t; cvta.to.shared.u64 t, %1; cvt.u32.u64 %0, t; }"
        : "=r"(a) : "l"(p));
    return a;
}
__device__ __forceinline__ uint32_t f2tf(float f) {
    uint32_t r;
    asm("cvt.rna.tf32.f32 %0, %1;" : "=r"(r) : "f"(f));
    return r;
}
__device__ __forceinline__ float ex2(float x) {
    float y;
    asm("ex2.approx.f32 %0, %1;" : "=f"(y) : "f"(x));
    return y;
}
__device__ __forceinline__ void mma_tf32(float c[4],
                                         uint32_t a0, uint32_t a1,
                                         uint32_t a2, uint32_t a3,
                                         uint32_t b0, uint32_t b1)
{
    asm volatile(
        "mma.sync.aligned.m16n8k8.row.col.f32.tf32.tf32.f32 "
        "{%0,%1,%2,%3},{%4,%5,%6,%7},{%8,%9},{%0,%1,%2,%3};"
        : "+f"(c[0]), "+f"(c[1]), "+f"(c[2]), "+f"(c[3])
        : "r"(a0), "r"(a1), "r"(a2), "r"(a3), "r"(b0), "r"(b1));
}
#define CP_ASYNC16(dst_u32, src_ptr) \
    asm volatile("cp.async.cg.shared.global [%0], [%1], 16;" \
                 :: "r"(dst_u32), "l"(src_ptr))
#define CP_COMMIT() asm volatile("cp.async.commit_group;" ::: "memory")
#define CP_WAIT2()  asm volatile("cp.async.wait_group 2;" ::: "memory")
#define CP_WAIT0()  asm volatile("cp.async.wait_group 0;" ::: "memory")

// ===========================================================================
// elementwise tf32 pre-rounding (rna)
// ===========================================================================
__global__ __launch_bounds__(256)
void round_tf32_kernel(const float* __restrict__ in, float* __restrict__ out,
                       int n)
{
    int i = (blockIdx.x * 256 + threadIdx.x) * 4;
    if (i < n) {
        float4 v = *(const float4*)(in + i);
        float4 o;
        o.x = __uint_as_float(f2tf(v.x));
        o.y = __uint_as_float(f2tf(v.y));
        o.z = __uint_as_float(f2tf(v.z));
        o.w = __uint_as_float(f2tf(v.w));
        *(float4*)(out + i) = o;
    }
}

// ===========================================================================
// tf32 mma GEMM, 4-stage cp.async pipeline, fragment double-buffer.
// C[M,N] = A[M,K] @ B[N,K]^T + bias[N]; A,B pre-rounded to tf32.
// BM=BN=128, BK=16, 128 threads (4 warps), warp tile 64x64.
// round_out: write C values tf32-rounded (feeds next cp.async GEMM/attn).
// ===========================================================================
#define GSTRIDE 20
#define STAGE_WORDS (128 * GSTRIDE)
#define STAGE_PAIR  (2 * STAGE_WORDS)
#define GEMM_SMEM_BYTES (4 * STAGE_PAIR * 4)   // 81920

__global__ __launch_bounds__(128, 2)
void gemm_mma(const float* __restrict__ A,
              const float* __restrict__ B,
              const float* __restrict__ bias,
              float* __restrict__ C,
              int M, int N, int K, int round_out)
{
    extern __shared__ uint32_t sm[];
    const uint32_t smem_base = smem_u32(sm);

    const int tid  = threadIdx.x;
    const int lane = tid & 31;
    const int wid  = tid >> 5;
    const int g    = lane >> 2;
    const int t    = lane & 3;
    const int wm   = wid >> 1;
    const int wn   = wid & 1;

    const int row0 = blockIdx.y * 128;
    const int col0 = blockIdx.x * 128;
    const int NT   = K / 16;

    const int lr = tid >> 2;
    const int lc = tid & 3;
    const float* Ab = A + (size_t)row0 * K;
    const float* Bb = B + (size_t)col0 * K;
    uint32_t so[4];
    #pragma unroll
    for (int i = 0; i < 4; i++)
        so[i] = ((i * 32 + lr) * GSTRIDE + lc * 4) * 4;

    #define ISSUE_STAGE(kt, s) do { \
        const uint32_t sa = smem_base + (uint32_t)(s) * (STAGE_PAIR * 4); \
        const uint32_t sb = sa + STAGE_WORDS * 4; \
        const int ko = (kt) * 16 + lc * 4; \
        _Pragma("unroll") \
        for (int i = 0; i < 4; i++) { \
            CP_ASYNC16(sa + so[i], Ab + (size_t)(i * 32 + lr) * K + ko); \
            CP_ASYNC16(sb + so[i], Bb + (size_t)(i * 32 + lr) * K + ko); \
        } \
    } while (0)

    float acc[4][8][4];
    #pragma unroll
    for (int mf = 0; mf < 4; mf++)
        #pragma unroll
        for (int nf = 0; nf < 8; nf++)
            #pragma unroll
            for (int c = 0; c < 4; c++) acc[mf][nf][c] = 0.f;

    ISSUE_STAGE(0, 0); CP_COMMIT();
    ISSUE_STAGE(1, 1); CP_COMMIT();
    ISSUE_STAGE(2, 2); CP_COMMIT();

    for (int kt = 0; kt < NT; kt++) {
        if (kt + 3 < NT) ISSUE_STAGE(kt + 3, (kt + 3) & 3);
        CP_COMMIT();
        CP_WAIT2();
        __syncthreads();

        const uint32_t* sA = sm + (kt & 3) * STAGE_PAIR;
        const uint32_t* sB = sA + STAGE_WORDS;

        uint32_t afr[2][4][4], bfr[2][8][2];

        #define LOAD_FRAGS(buf, kk) do { \
            _Pragma("unroll") \
            for (int mf = 0; mf < 4; mf++) { \
                const int rb = wm * 64 + mf * 16; \
                afr[buf][mf][0] = sA[(rb + g)     * GSTRIDE + (kk) + t]; \
                afr[buf][mf][1] = sA[(rb + g + 8) * GSTRIDE + (kk) + t]; \
                afr[buf][mf][2] = sA[(rb + g)     * GSTRIDE + (kk) + t + 4]; \
                afr[buf][mf][3] = sA[(rb + g + 8) * GSTRIDE + (kk) + t + 4]; \
            } \
            _Pragma("unroll") \
            for (int nf = 0; nf < 8; nf++) { \
                const int nb = wn * 64 + nf * 8 + g; \
                bfr[buf][nf][0] = sB[nb * GSTRIDE + (kk) + t]; \
                bfr[buf][nf][1] = sB[nb * GSTRIDE + (kk) + t + 4]; \
            } \
        } while (0)

        #define DO_MMAS(buf) do { \
            _Pragma("unroll") \
            for (int mf = 0; mf < 4; mf++) \
                _Pragma("unroll") \
                for (int nf = 0; nf < 8; nf++) \
                    mma_tf32(acc[mf][nf], \
                             afr[buf][mf][0], afr[buf][mf][1], \
                             afr[buf][mf][2], afr[buf][mf][3], \
                             bfr[buf][nf][0], bfr[buf][nf][1]); \
        } while (0)

        LOAD_FRAGS(0, 0);
        LOAD_FRAGS(1, 8);
        DO_MMAS(0);
        DO_MMAS(1);

        #undef LOAD_FRAGS
        #undef DO_MMAS
        __syncthreads();
    }

    #pragma unroll
    for (int mf = 0; mf < 4; mf++) {
        const int r0 = row0 + wm * 64 + mf * 16 + g;
        #pragma unroll
        for (int nf = 0; nf < 8; nf++) {
            const int col = col0 + wn * 64 + nf * 8 + 2 * t;
            const float b0 = bias[col], b1 = bias[col + 1];
            float v0 = acc[mf][nf][0] + b0, v1 = acc[mf][nf][1] + b1;
            float v2 = acc[mf][nf][2] + b0, v3 = acc[mf][nf][3] + b1;
            if (round_out) {
                v0 = __uint_as_float(f2tf(v0));
                v1 = __uint_as_float(f2tf(v1));
                v2 = __uint_as_float(f2tf(v2));
                v3 = __uint_as_float(f2tf(v3));
            }
            *(float2*)(C + (size_t)r0 * N + col)       = make_float2(v0, v1);
            *(float2*)(C + (size_t)(r0 + 8) * N + col) = make_float2(v2, v3);
        }
    }
}

// ===========================================================================
// tf32 mma causal flash attention.
// XOR-swizzled SMEM (stride 64, no padding): 64KB total -> 3 CTAs/SM.
// Q/K/P swizzle: col ^ ((row&7)<<2).  V swizzle: col ^ ((row&3)<<3).
// K/V tiles loaded raw via cp.async (qkv pre-rounded by GEMM1 epilogue).
// 1-D grid, heavy q-tiles first.
// ===========================================================================
#define QS_OFF 0
#define KS_OFF (64 * 64)
#define VS_OFF (KS_OFF + 64 * 64)
#define PS_OFF (VS_OFF + 64 * 64)
#define ATTN_SMEM_WORDS (PS_OFF + 64 * 64)
#define ATTN_SMEM_BYTES (ATTN_SMEM_WORDS * 4)   // 65536

__global__ __launch_bounds__(128, 3)
void attn_mma(const float* __restrict__ qkv, float* __restrict__ outp)
{
    extern __shared__ uint32_t smab[];
    uint32_t* Qs = smab + QS_OFF;
    uint32_t* Ks = smab + KS_OFF;
    uint32_t* Vs = smab + VS_OFF;
    uint32_t* Ps = smab + PS_OFF;
    const uint32_t ks_base = smem_u32(Ks);
    const uint32_t vs_base = smem_u32(Vs);

    const int tid  = threadIdx.x;
    const int lane = tid & 31;
    const int w    = tid >> 5;
    const int g    = lane >> 2;
    const int t    = lane & 3;
    const int g4   = g << 2;
    const int t8   = t << 3;

    // heavy q-tiles first: bid 0 -> qt 31
    const int bid = blockIdx.x;
    const int qt  = 31 - (bid >> 5);
    const int yz  = bid & 31;
    const int h   = yz & 15;
    const int b   = yz >> 4;
    const int q0  = qt * 64;

    const float SCALE = 0.125f * 1.44269504088896f;

    // ---- load Q tile (scaled, rounded, swizzled) ----
    {
        const float* qb = qkv + (size_t)(b * SEQ + q0) * QKVDIM + h * HD;
        #pragma unroll
        for (int i = 0; i < 8; i++) {
            int f = i * 128 + tid;
            int row = f >> 4, c4 = (f & 15) * 4;
            int c4s = c4 ^ ((row & 7) << 2);
            float4 v = *(const float4*)(qb + (size_t)row * QKVDIM + c4);
            uint4 u;
            u.x = f2tf(v.x * SCALE); u.y = f2tf(v.y * SCALE);
            u.z = f2tf(v.z * SCALE); u.w = f2tf(v.w * SCALE);
            *(uint4*)&Qs[row * 64 + c4s] = u;
        }
    }

    float m0 = -1e30f, m1 = -1e30f, l0 = 0.f, l1 = 0.f;
    float O[8][4];
    #pragma unroll
    for (int nf = 0; nf < 8; nf++)
        #pragma unroll
        for (int c = 0; c < 4; c++) O[nf][c] = 0.f;

    const int qrow  = (w * 16 + g) * 64;       // Q/P row base (words)
    const int qrow8 = (w * 16 + g + 8) * 64;

    for (int kv0 = 0; kv0 <= q0; kv0 += 64) {
        __syncthreads();   // prior compute done -> K/V stages free
        {
            const float* kb = qkv + (size_t)(b * SEQ + kv0) * QKVDIM + DMODEL + h * HD;
            const float* vb = kb + DMODEL;
            #pragma unroll
            for (int i = 0; i < 8; i++) {
                int f = i * 128 + tid;
                int row = f >> 4, c4 = (f & 15) * 4;
                int kc4 = c4 ^ ((row & 7) << 2);
                int vc4 = c4 ^ ((row & 3) << 3);
                CP_ASYNC16(ks_base + (uint32_t)(row * 64 + kc4) * 4,
                           kb + (size_t)row * QKVDIM + c4);
                CP_ASYNC16(vs_base + (uint32_t)(row * 64 + vc4) * 4,
                           vb + (size_t)row * QKVDIM + c4);
            }
        }
        CP_COMMIT();
        CP_WAIT0();
        __syncthreads();

        // ---- S = Q K^T ----
        float s[8][4];
        #pragma unroll
        for (int nf = 0; nf < 8; nf++)
            #pragma unroll
            for (int c = 0; c < 4; c++) s[nf][c] = 0.f;

        #pragma unroll
        for (int kk = 0; kk < 64; kk += 8) {
            uint32_t a0 = Qs[qrow  + ((kk + t) ^ g4)];
            uint32_t a1 = Qs[qrow8 + ((kk + t) ^ g4)];
            uint32_t a2 = Qs[qrow  + ((kk + t + 4) ^ g4)];
            uint32_t a3 = Qs[qrow8 + ((kk + t + 4) ^ g4)];
            #pragma unroll
            for (int nf = 0; nf < 8; nf++) {
                uint32_t b0 = Ks[(nf * 8 + g) * 64 + ((kk + t) ^ g4)];
                uint32_t b1 = Ks[(nf * 8 + g) * 64 + ((kk + t + 4) ^ g4)];
                mma_tf32(s[nf], a0, a1, a2, a3, b0, b1);
            }
        }

        // ---- causal mask (diagonal block only) ----
        const int r0 = q0 + w * 16 + g;
        const int r1 = r0 + 8;
        if (kv0 == q0) {
            #pragma unroll
            for (int nf = 0; nf < 8; nf++) {
                int c0 = kv0 + nf * 8 + 2 * t;
                if (c0     > r0) s[nf][0] = -1e30f;
                if (c0 + 1 > r0) s[nf][1] = -1e30f;
                if (c0     > r1) s[nf][2] = -1e30f;
                if (c0 + 1 > r1) s[nf][3] = -1e30f;
            }
        }

        // ---- online softmax (exp2 domain) ----
        float rm0 = -1e30f, rm1 = -1e30f;
        #pragma unroll
        for (int nf = 0; nf < 8; nf++) {
            rm0 = fmaxf(rm0, fmaxf(s[nf][0], s[nf][1]));
            rm1 = fmaxf(rm1, fmaxf(s[nf][2], s[nf][3]));
        }
        rm0 = fmaxf(rm0, __shfl_xor_sync(0xffffffffu, rm0, 1));
        rm0 = fmaxf(rm0, __shfl_xor_sync(0xffffffffu, rm0, 2));
        rm1 = fmaxf(rm1, __shfl_xor_sync(0xffffffffu, rm1, 1));
        rm1 = fmaxf(rm1, __shfl_xor_sync(0xffffffffu, rm1, 2));

        float mn0 = fmaxf(m0, rm0), mn1 = fmaxf(m1, rm1);
        float f0 = ex2(m0 - mn0), f1 = ex2(m1 - mn1);
        l0 *= f0; l1 *= f1;
        #pragma unroll
        for (int nf = 0; nf < 8; nf++) {
            O[nf][0] *= f0; O[nf][1] *= f0;
            O[nf][2] *= f1; O[nf][3] *= f1;
        }

        float sum0 = 0.f, sum1 = 0.f;
        #pragma unroll
        for (int nf = 0; nf < 8; nf++) {
            float p0 = ex2(s[nf][0] - mn0);
            float p1 = ex2(s[nf][1] - mn0);
            float p2 = ex2(s[nf][2] - mn1);
            float p3 = ex2(s[nf][3] - mn1);
            sum0 += p0 + p1; sum1 += p2 + p3;
            int cis = (nf * 8 + 2 * t) ^ g4;
            Ps[qrow  + cis] = f2tf(p0); Ps[qrow  + cis + 1] = f2tf(p1);
            Ps[qrow8 + cis] = f2tf(p2); Ps[qrow8 + cis + 1] = f2tf(p3);
        }
        sum0 += __shfl_xor_sync(0xffffffffu, sum0, 1);
        sum0 += __shfl_xor_sync(0xffffffffu, sum0, 2);
        sum1 += __shfl_xor_sync(0xffffffffu, sum1, 1);
        sum1 += __shfl_xor_sync(0xffffffffu, sum1, 2);
        l0 += sum0; l1 += sum1;
        m0 = mn0; m1 = mn1;

        __syncwarp();

        // ---- O += P V ----
        #pragma unroll
        for (int kk = 0; kk < 64; kk += 8) {
            uint32_t a0 = Ps[qrow  + ((kk + t) ^ g4)];
            uint32_t a1 = Ps[qrow8 + ((kk + t) ^ g4)];
            uint32_t a2 = Ps[qrow  + ((kk + t + 4) ^ g4)];
            uint32_t a3 = Ps[qrow8 + ((kk + t + 4) ^ g4)];
            #pragma unroll
            for (int nf = 0; nf < 8; nf++) {
                int col = (nf * 8 + g) ^ t8;
                uint32_t b0 = Vs[(kk + t) * 64 + col];
                uint32_t b1 = Vs[(kk + t + 4) * 64 + col];
                mma_tf32(O[nf], a0, a1, a2, a3, b0, b1);
            }
        }
    }

    // ---- epilogue: write tf32-rounded (feeds cp.async proj GEMM) ----
    const float inv0 = 1.f / l0, inv1 = 1.f / l1;
    const size_t orow0 = (size_t)(b * SEQ + q0 + w * 16 + g);
    const size_t orow1 = orow0 + 8;
    #pragma unroll
    for (int nf = 0; nf < 8; nf++) {
        const int col = h * HD + nf * 8 + 2 * t;
        *(float2*)(outp + orow0 * DMODEL + col) =
            make_float2(__uint_as_float(f2tf(O[nf][0] * inv0)),
                        __uint_as_float(f2tf(O[nf][1] * inv0)));
        *(float2*)(outp + orow1 * DMODEL + col) =
            make_float2(__uint_as_float(f2tf(O[nf][2] * inv1)),
                        __uint_as_float(f2tf(O[nf][3] * inv1)));
    }
}

// ---------------------------------------------------------------------------
extern "C" void kernel_launch(void* const* d_in, const int* in_sizes, int n_in,
                              void* d_out, int out_size)
{
    const float* x    = (const float*)d_in[0];
    const float* Wqkv = (const float*)d_in[1];
    const float* bqkv = (const float*)d_in[2];
    const float* Wd   = (const float*)d_in[3];
    const float* bd   = (const float*)d_in[4];
    float* out = (float*)d_out;

    float *qkv_buf, *attn_buf, *xr, *wqkvr, *wdr;
    cudaGetSymbolAddress((void**)&qkv_buf,  g_qkv);
    cudaGetSymbolAddress((void**)&attn_buf, g_attn);
    cudaGetSymbolAddress((void**)&xr,       g_xr);
    cudaGetSymbolAddress((void**)&wqkvr,    g_wqkvr);
    cudaGetSymbolAddress((void**)&wdr,      g_wdr);

    const int M = BATCH * SEQ;   // 4096

    cudaFuncSetAttribute(gemm_mma,
                         cudaFuncAttributeMaxDynamicSharedMemorySize,
                         GEMM_SMEM_BYTES);
    cudaFuncSetAttribute(attn_mma,
                         cudaFuncAttributeMaxDynamicSharedMemorySize,
                         ATTN_SMEM_BYTES);

    // 0) pre-round GEMM inputs to tf32 (rna)
    const int nx = M * DMODEL, nwq = QKVDIM * DMODEL, nwd = DMODEL * DMODEL;
    round_tf32_kernel<<<(nx / 4 + 255) / 256, 256>>>(x, xr, nx);
    round_tf32_kernel<<<(nwq / 4 + 255) / 256, 256>>>(Wqkv, wqkvr, nwq);
    round_tf32_kernel<<<(nwd / 4 + 255) / 256, 256>>>(Wd, wdr, nwd);

    // 1) QKV projection (writes tf32-rounded qkv)
    gemm_mma<<<dim3(QKVDIM / 128, M / 128), 128, GEMM_SMEM_BYTES>>>(
        xr, wqkvr, bqkv, qkv_buf, M, QKVDIM, DMODEL, 1);

    // 2) Causal attention (writes tf32-rounded)
    attn_mma<<<SEQ / 64 * NHEADS * BATCH, 128, ATTN_SMEM_BYTES>>>(
        qkv_buf, attn_buf);

    // 3) Output projection (full fp32 out)
    gemm_mma<<<dim3(DMODEL / 128, M / 128), 128, GEMM_SMEM_BYTES>>>(
        attn_buf, wdr, bd, out, M, DMODEL, DMODEL, 0);
}